// round 16
// baseline (speedup 1.0000x reference)
#include <cuda_runtime.h>
#include <cuda_fp16.h>
#include <cstdint>

#define T_STEPS 30
#define HID     1024
#define LAYERS  4
#define ZCOLS   4096
#define BH      (256 * HID)
#define NSTEPS  (T_STEPS * LAYERS)   // 120

#define KC          128               // fp16 k-elements per stage (2 SW128 panels)
#define NCHUNK      32                // 4 segments * (1024/128)
#define A_BYTES     16384
#define B_BYTES     32768
#define A_PANEL     8192
#define B_PANEL     16384
#define STAGE_BYTES (A_BYTES + B_BYTES)          // 49152
#define SMEM_BYTES  (3 * STAGE_BYTES)            // 147456
#define GRID_CTAS   128

// ---------------- scratch (__device__ globals) ----------------
__device__ __half g_w[2][LAYERS][ZCOLS * HID];   // [kern/rec][layer][n'][k] fp16
__device__ __half g_xh[T_STEPS * BH];
__device__ __half g_xl[T_STEPS * BH];
__device__ float  g_c[LAYERS][BH];
__device__ __half g_hh[LAYERS][2][BH];
__device__ __half g_hl[LAYERS][2][BH];
__device__ __half g_curh[2][BH];
__device__ __half g_curl[2][BH];
__device__ float  g_biasp[LAYERS][ZCOLS];
__device__ unsigned g_flags[GRID_CTAS * 8];      // 32B-strided per-CTA step flags

// ---------------- helpers ----------------
__device__ __forceinline__ uint32_t smem_u32(const void* p) {
    uint32_t a;
    asm("{ .reg .u64 t; cvta.to.shared.u64 t, %1; cvt.u32.u64 %0, t; }" : "=r"(a) : "l"(p));
    return a;
}
__device__ __forceinline__ void cp16(uint32_t dst, const void* src) {
    asm volatile("cp.async.cg.shared.global [%0], [%1], 16;"
                 :: "r"(dst), "l"(__cvta_generic_to_global(src)) : "memory");
}
__device__ __forceinline__ uint32_t sw128(uint32_t off) { return off ^ ((off >> 3) & 0x70); }
__device__ __forceinline__ void ldmat4(uint32_t addr, uint32_t& r0, uint32_t& r1,
                                       uint32_t& r2, uint32_t& r3) {
    asm volatile("ldmatrix.sync.aligned.m8n8.x4.shared.b16 {%0,%1,%2,%3}, [%4];"
                 : "=r"(r0), "=r"(r1), "=r"(r2), "=r"(r3) : "r"(addr));
}
__device__ __forceinline__ void mma_f16(float& d0, float& d1, float& d2, float& d3,
                                        uint32_t a0, uint32_t a1, uint32_t a2, uint32_t a3,
                                        uint32_t b0, uint32_t b1) {
    asm volatile("mma.sync.aligned.m16n8k16.row.col.f32.f16.f16.f32 "
                 "{%0,%1,%2,%3},{%4,%5,%6,%7},{%8,%9},{%0,%1,%2,%3};"
                 : "+f"(d0), "+f"(d1), "+f"(d2), "+f"(d3)
                 : "r"(a0), "r"(a1), "r"(a2), "r"(a3), "r"(b0), "r"(b1));
}
// fp16 accumulator variant: D/C are 2 regs of packed f16x2
__device__ __forceinline__ void mma_h16(uint32_t& c0, uint32_t& c1,
                                        uint32_t a0, uint32_t a1, uint32_t a2, uint32_t a3,
                                        uint32_t b0, uint32_t b1) {
    asm volatile("mma.sync.aligned.m16n8k16.row.col.f16.f16.f16.f16 "
                 "{%0,%1},{%2,%3,%4,%5},{%6,%7},{%0,%1};"
                 : "+r"(c0), "+r"(c1)
                 : "r"(a0), "r"(a1), "r"(a2), "r"(a3), "r"(b0), "r"(b1));
}
__device__ __forceinline__ void split_h(float x, uint32_t& hi, uint32_t& lo) {
    __half h = __float2half(x);
    __half l = __float2half(x - __half2float(h));
    hi = (uint32_t)__half_as_ushort(h);
    lo = (uint32_t)__half_as_ushort(l);
}

struct Ptrs {
    const __half *ah, *al, *hhp, *hlp, *w1, *w2;
};
__device__ __forceinline__ void get_ptrs(int step, Ptrs& P) {
    int t = step >> 2, j = step & 3;
    P.ah  = (j == 0) ? g_xh + (size_t)t * BH : g_curh[j & 1];
    P.al  = (j == 0) ? g_xl + (size_t)t * BH : g_curl[j & 1];
    P.hhp = g_hh[j][t & 1];
    P.hlp = g_hl[j][t & 1];
    P.w1  = g_w[0][j];
    P.w2  = g_w[1][j];
}
__device__ __forceinline__ const __half* selA(const Ptrs& P, int p) {
    return (p == 0) ? P.ah : (p == 1) ? P.al : (p == 2) ? P.hhp : P.hlp;
}
__device__ __forceinline__ const __half* selB(const Ptrs& P, int p) {
    return (p < 2) ? P.w1 : P.w2;
}

// ---------------- init kernels ----------------
__global__ void zero_state_kernel() {
    int i = blockIdx.x * blockDim.x + threadIdx.x;
    if (i < GRID_CTAS * 8) g_flags[i] = 0u;
    int nc = LAYERS * BH;
    int nh = LAYERS * 2 * BH / 2;
    if (i < nc) ((float*)g_c)[i] = 0.0f;
    if (i < nh) { ((uint32_t*)g_hh)[i] = 0u; ((uint32_t*)g_hl)[i] = 0u; }
}

__global__ void bias_perm_kernel(const float* __restrict__ bias) {
    int i = blockIdx.x * blockDim.x + threadIdx.x;
    if (i >= LAYERS * ZCOLS) return;
    int l = i >> 12, n = i & 4095;
    g_biasp[l][4 * (n & 1023) + (n >> 10)] = bias[i];
}

__global__ void wconv_kernel(const float* __restrict__ kern, const float* __restrict__ rec) {
    __shared__ float t[32][33];
    int mat = blockIdx.z >> 2;
    int l   = blockIdx.z & 3;
    const float* src = (mat ? rec : kern) + (size_t)l * HID * ZCOLS;
    int n0 = blockIdx.x * 32, k0 = blockIdx.y * 32;
    int tx = threadIdx.x, ty = threadIdx.y;
    #pragma unroll
    for (int i = 0; i < 4; i++)
        t[ty + i * 8][tx] = src[(size_t)(k0 + ty + i * 8) * ZCOLS + n0 + tx];
    __syncthreads();
    __half* o = g_w[mat][l];
    #pragma unroll
    for (int i = 0; i < 4; i++) {
        int n  = n0 + ty + i * 8;
        int np = 4 * (n & 1023) + (n >> 10);
        o[(size_t)np * HID + k0 + tx] = __float2half(t[tx][ty + i * 8]);
    }
}

__global__ void xsplit_kernel(const float* __restrict__ x) {
    int i = blockIdx.x * blockDim.x + threadIdx.x;
    if (i >= T_STEPS * BH) return;
    float v = x[i];
    __half h = __float2half(v);
    g_xh[i] = h;
    g_xl[i] = __float2half(v - __half2float(h));
}

// ---------------- persistent fused LSTM ----------------
__global__ __launch_bounds__(256, 1) void lstm_persistent_kernel(float* __restrict__ out)
{
    extern __shared__ char smem[];
    const uint32_t sb = smem_u32(smem);
    const int tid  = threadIdx.x;
    const int lane = tid & 31;
    const int wid  = tid >> 5;
    const int wm = wid >> 2;
    const int wn = wid & 3;
    const int blockN   = blockIdx.x * 128;
    const int blockRow = blockIdx.y * 64;
    const int ctaid    = blockIdx.y * 32 + blockIdx.x;

    // cp.async load maps
    const int ld_row = tid >> 3;
    const int ld_c16 = tid & 7;
    uint32_t aDst[2], bDst[4];
    #pragma unroll
    for (int r = 0; r < 2; r++)
        aDst[r] = sw128((uint32_t)((ld_row + r * 32) * 128 + ld_c16 * 16));
    #pragma unroll
    for (int r = 0; r < 4; r++)
        bDst[r] = A_BYTES + sw128((uint32_t)((ld_row + r * 32) * 128 + ld_c16 * 16));

    uint32_t aBase[2], bBase[2];
    {
        int mA = wm * 32 + (lane & 7) + ((lane >> 3) & 1) * 8;
        int kA = (lane >> 4) * 16;
        int nB = wn * 32 + (lane & 7) + ((lane >> 4) & 1) * 8;
        int kB = ((lane >> 3) & 1) * 16;
        #pragma unroll
        for (int mi = 0; mi < 2; mi++) {
            int row = mA + mi * 16;
            aBase[mi] = (uint32_t)(row * 128) + ((uint32_t)kA ^ ((uint32_t)(row & 7) * 16));
        }
        #pragma unroll
        for (int nh2 = 0; nh2 < 2; nh2++) {
            int row = nB + nh2 * 16;
            bBase[nh2] = A_BYTES + (uint32_t)(row * 128) + ((uint32_t)kB ^ ((uint32_t)(row & 7) * 16));
        }
    }

    auto loadA = [&](const Ptrs& P, int jc, int s) {
        int p = jc >> 3, k0 = (jc & 7) * KC;
        const __half* As = selA(P, p);
        uint32_t base = sb + (uint32_t)s * STAGE_BYTES;
        #pragma unroll
        for (int pi = 0; pi < 2; pi++)
            #pragma unroll
            for (int r = 0; r < 2; r++)
                cp16(base + pi * A_PANEL + aDst[r],
                     As + (size_t)(blockRow + ld_row + r * 32) * HID + k0 + pi * 64 + ld_c16 * 8);
    };
    auto loadB = [&](const Ptrs& P, int jc, int s) {
        int p = jc >> 3, k0 = (jc & 7) * KC;
        const __half* Bs = selB(P, p);
        uint32_t base = sb + (uint32_t)s * STAGE_BYTES;
        #pragma unroll
        for (int pi = 0; pi < 2; pi++)
            #pragma unroll
            for (int r = 0; r < 4; r++)
                cp16(base + pi * B_PANEL + bDst[r],
                     Bs + (size_t)(blockN + ld_row + r * 32) * HID + k0 + pi * 64 + ld_c16 * 8);
    };

    auto ldsm_ks = [&](uint32_t base, int ks, uint32_t a[2][4], uint32_t bt[2][4]) {
        uint32_t xk  = (uint32_t)((ks & 3) * 32);
        uint32_t pkA = (uint32_t)((ks >> 2) * A_PANEL);
        uint32_t pkB = (uint32_t)((ks >> 2) * B_PANEL);
        #pragma unroll
        for (int mi = 0; mi < 2; mi++)
            ldmat4(base + pkA + (aBase[mi] ^ xk), a[mi][0], a[mi][1], a[mi][2], a[mi][3]);
        #pragma unroll
        for (int nh2 = 0; nh2 < 2; nh2++)
            ldmat4(base + pkB + (bBase[nh2] ^ xk), bt[nh2][0], bt[nh2][1], bt[nh2][2], bt[nh2][3]);
    };

    // prologue: prefetch chunks 0,1
    Ptrs P;
    get_ptrs(0, P);
    loadB(P, 0, 0); asm volatile("cp.async.commit_group;" ::: "memory");
    loadB(P, 1, 1); asm volatile("cp.async.commit_group;" ::: "memory");
    loadA(P, 0, 0); asm volatile("cp.async.commit_group;" ::: "memory");
    loadA(P, 1, 1); asm volatile("cp.async.commit_group;" ::: "memory");

    #pragma unroll 1
    for (int step = 0; step < NSTEPS; step++) {
        const int t = step >> 2;
        const int j = step & 3;
        get_ptrs(step, P);

        float d[2][4][4];          // fp32 accum: segments 0,2 (Ah*W1, Hh*W2)
        uint32_t e[2][4][2];       // fp16 accum: segments 1,3 (Al*W1, Hl*W2)
        #pragma unroll
        for (int mi = 0; mi < 2; mi++)
            #pragma unroll
            for (int ni = 0; ni < 4; ni++) {
                #pragma unroll
                for (int r = 0; r < 4; r++) d[mi][ni][r] = 0.0f;
                e[mi][ni][0] = 0u; e[mi][ni][1] = 0u;
            }

        int s_cmp = 0, s_load = 2;
        #pragma unroll 1
        for (int i = 0; i < NCHUNK; i++) {
            asm volatile("cp.async.wait_group 1;" ::: "memory");
            __syncthreads();
            if (i + 2 < NCHUNK) { loadA(P, i + 2, s_load); loadB(P, i + 2, s_load); }
            asm volatile("cp.async.commit_group;" ::: "memory");

            uint32_t base = sb + (uint32_t)s_cmp * STAGE_BYTES;
            uint32_t a[2][2][4], bt[2][2][4];
            ldsm_ks(base, 0, a[0], bt[0]);
            if (((i >> 3) & 1) == 0) {          // main segments -> fp32 accum
                #pragma unroll
                for (int ks = 0; ks < 8; ks++) {
                    int cur = ks & 1;
                    if (ks < 7) ldsm_ks(base, ks + 1, a[cur ^ 1], bt[cur ^ 1]);
                    #pragma unroll
                    for (int mi = 0; mi < 2; mi++)
                        #pragma unroll
                        for (int ni = 0; ni < 4; ni++)
                            mma_f16(d[mi][ni][0], d[mi][ni][1], d[mi][ni][2], d[mi][ni][3],
                                    a[cur][mi][0], a[cur][mi][1], a[cur][mi][2], a[cur][mi][3],
                                    bt[cur][ni >> 1][(ni & 1) * 2], bt[cur][ni >> 1][(ni & 1) * 2 + 1]);
                }
            } else {                            // correction segments -> fp16 accum
                #pragma unroll
                for (int ks = 0; ks < 8; ks++) {
                    int cur = ks & 1;
                    if (ks < 7) ldsm_ks(base, ks + 1, a[cur ^ 1], bt[cur ^ 1]);
                    #pragma unroll
                    for (int mi = 0; mi < 2; mi++)
                        #pragma unroll
                        for (int ni = 0; ni < 4; ni++)
                            mma_h16(e[mi][ni][0], e[mi][ni][1],
                                    a[cur][mi][0], a[cur][mi][1], a[cur][mi][2], a[cur][mi][3],
                                    bt[cur][ni >> 1][(ni & 1) * 2], bt[cur][ni >> 1][(ni & 1) * 2 + 1]);
                }
            }
            if (++s_cmp == 3) s_cmp = 0;
            if (++s_load == 3) s_load = 0;
        }

        // fold fp16 corrections into fp32 accumulators
        #pragma unroll
        for (int mi = 0; mi < 2; mi++)
            #pragma unroll
            for (int ni = 0; ni < 4; ni++) {
                __half2 p0 = *reinterpret_cast<__half2*>(&e[mi][ni][0]);
                __half2 p1 = *reinterpret_cast<__half2*>(&e[mi][ni][1]);
                d[mi][ni][0] += __low2float(p0);
                d[mi][ni][1] += __high2float(p0);
                d[mi][ni][2] += __low2float(p1);
                d[mi][ni][3] += __high2float(p1);
            }

        asm volatile("cp.async.wait_group 0;" ::: "memory");
        __syncthreads();

        // stage accumulators: per-warp [32 rows][33 floats]
        float* st = (float*)(smem + (size_t)wid * 32 * 33 * 4);
        #pragma unroll
        for (int mi = 0; mi < 2; mi++) {
            int r0 = mi * 16 + (lane >> 2);
            #pragma unroll
            for (int ni = 0; ni < 4; ni++) {
                int c0 = ni * 8 + 2 * (lane & 3);
                st[r0 * 33 + c0]           = d[mi][ni][0];
                st[r0 * 33 + c0 + 1]       = d[mi][ni][1];
                st[(r0 + 8) * 33 + c0]     = d[mi][ni][2];
                st[(r0 + 8) * 33 + c0 + 1] = d[mi][ni][3];
            }
        }
        __syncwarp();

        // gate math
        {
            const float* zrow = st + lane * 33;
            const int m  = blockRow + wm * 32 + lane;
            const int ug = (blockN >> 2) + wn * 8;
            const float4* bq = (const float4*)(&g_biasp[j][blockN + wn * 32]);
            float* cp = &g_c[j][(size_t)m * HID + ug];
            float4 co0 = *(const float4*)(cp);
            float4 co1 = *(const float4*)(cp + 4);
            float cold[8] = {co0.x, co0.y, co0.z, co0.w, co1.x, co1.y, co1.z, co1.w};
            float cn[8], hn[8];
            #pragma unroll
            for (int k = 0; k < 8; k++) {
                float4 bb = bq[k];
                float zi = zrow[4 * k]     + bb.x;
                float zf = zrow[4 * k + 1] + bb.y;
                float zg = zrow[4 * k + 2] + bb.z;
                float zo = zrow[4 * k + 3] + bb.w;
                float ig = 1.0f / (1.0f + __expf(-zi));
                float fg = 1.0f / (1.0f + __expf(-zf));
                float gg = tanhf(zg);
                float og = 1.0f / (1.0f + __expf(-zo));
                float c_ = fg * cold[k] + ig * gg;
                cn[k] = c_;
                hn[k] = og * tanhf(c_);
            }
            *(float4*)(cp)     = make_float4(cn[0], cn[1], cn[2], cn[3]);
            *(float4*)(cp + 4) = make_float4(cn[4], cn[5], cn[6], cn[7]);

            uint32_t chi[8], clo[8], hhi[8], hlo[8];
            #pragma unroll
            for (int k = 0; k < 8; k++) {
                split_h(cn[k], chi[k], clo[k]);
                split_h(hn[k], hhi[k], hlo[k]);
            }
            size_t so = (size_t)m * HID + ug;
            __half* curh_o = g_curh[(j + 1) & 1];
            __half* curl_o = g_curl[(j + 1) & 1];
            __half* hh_o   = g_hh[j][(t + 1) & 1];
            __half* hl_o   = g_hl[j][(t + 1) & 1];
            uint4 v;
            v = make_uint4(chi[0] | (chi[1] << 16), chi[2] | (chi[3] << 16),
                           chi[4] | (chi[5] << 16), chi[6] | (chi[7] << 16));
            *(uint4*)(curh_o + so) = v;
            v = make_uint4(clo[0] | (clo[1] << 16), clo[2] | (clo[3] << 16),
                           clo[4] | (clo[5] << 16), clo[6] | (clo[7] << 16));
            *(uint4*)(curl_o + so) = v;
            v = make_uint4(hhi[0] | (hhi[1] << 16), hhi[2] | (hhi[3] << 16),
                           hhi[4] | (hhi[5] << 16), hhi[6] | (hhi[7] << 16));
            *(uint4*)(hh_o + so) = v;
            v = make_uint4(hlo[0] | (hlo[1] << 16), hlo[2] | (hlo[3] << 16),
                           hlo[4] | (hlo[5] << 16), hlo[6] | (hlo[7] << 16));
            *(uint4*)(hl_o + so) = v;

            if (step == NSTEPS - 1) {
                *(float4*)(out + so)     = make_float4(cn[0], cn[1], cn[2], cn[3]);
                *(float4*)(out + so + 4) = make_float4(cn[4], cn[5], cn[6], cn[7]);
            }
        }

        // -------- distributed-flag barrier + cross-step prefetch --------
        if (step < NSTEPS - 1) {
            __syncthreads();   // epilogue stores issued by all threads
            // signal own arrival (release: prior CTA stores visible via cumulativity)
            if (tid == 0)
                asm volatile("st.release.gpu.global.u32 [%0], %1;"
                             :: "l"(&g_flags[ctaid * 8]), "r"((unsigned)(step + 1)) : "memory");
            Ptrs Pn;
            get_ptrs(step + 1, Pn);
            // weights are state-independent: prefetch while others arrive
            loadB(Pn, 0, 0); asm volatile("cp.async.commit_group;" ::: "memory");
            loadB(Pn, 1, 1); asm volatile("cp.async.commit_group;" ::: "memory");
            // parallel poll: thread i waits for CTA i's flag
            if (tid < GRID_CTAS) {
                unsigned v;
                do {
                    asm volatile("ld.acquire.gpu.global.u32 %0, [%1];"
                                 : "=r"(v) : "l"(&g_flags[tid * 8]));
                } while (v < (unsigned)(step + 1));
            }
            __syncthreads();
            // activations depend on the step we just synced on
            loadA(Pn, 0, 0); asm volatile("cp.async.commit_group;" ::: "memory");
            loadA(Pn, 1, 1); asm volatile("cp.async.commit_group;" ::: "memory");
        }
    }
}

// ---------------- host launcher ----------------
extern "C" void kernel_launch(void* const* d_in, const int* in_sizes, int n_in,
                              void* d_out, int out_size)
{
    const float* inputs = (const float*)d_in[0];
    const float* kernel = (const float*)d_in[1];
    const float* rec    = (const float*)d_in[2];
    const float* bias   = (const float*)d_in[3];
    float* out = (float*)d_out;

    cudaFuncSetAttribute(lstm_persistent_kernel,
                         cudaFuncAttributeMaxDynamicSharedMemorySize, SMEM_BYTES);

    {
        int n = LAYERS * BH;
        zero_state_kernel<<<(n + 255) / 256, 256>>>();
        bias_perm_kernel<<<(LAYERS * ZCOLS + 255) / 256, 256>>>(bias);
        wconv_kernel<<<dim3(ZCOLS / 32, HID / 32, 2 * LAYERS), dim3(32, 8)>>>(kernel, rec);
        xsplit_kernel<<<(T_STEPS * BH + 255) / 256, 256>>>(inputs);
    }

    dim3 grid(32, 4);   // 128 CTAs, all resident — required by the barrier
    lstm_persistent_kernel<<<grid, 256, SMEM_BYTES>>>(out);
}

// round 17
// speedup vs baseline: 1.0496x; 1.0496x over previous
#include <cuda_runtime.h>
#include <cuda_fp16.h>
#include <cstdint>

#define T_STEPS 30
#define HID     1024
#define LAYERS  4
#define ZCOLS   4096
#define BH      (256 * HID)
#define NSTEPS  (T_STEPS * LAYERS)   // 120

#define KC          128               // fp16 k-elements per stage (2 SW128 panels)
#define NCHUNK      32                // 4 segments * (1024/128)
#define A_BYTES     16384
#define B_BYTES     32768
#define A_PANEL     8192
#define B_PANEL     16384
#define STAGE_BYTES (A_BYTES + B_BYTES)          // 49152
#define SMEM_BYTES  (3 * STAGE_BYTES)            // 147456
#define GRID_CTAS   128

// ---------------- scratch (__device__ globals) ----------------
__device__ __half g_w[2][LAYERS][ZCOLS * HID];   // [kern/rec][layer][n'][k] fp16
__device__ __half g_xh[T_STEPS * BH];
__device__ __half g_xl[T_STEPS * BH];
__device__ float  g_c[LAYERS][BH];
__device__ __half g_hh[LAYERS][2][BH];
__device__ __half g_hl[LAYERS][2][BH];
__device__ __half g_curh[2][BH];
__device__ __half g_curl[2][BH];
__device__ float  g_biasp[LAYERS][ZCOLS];
__device__ unsigned g_flags[GRID_CTAS * 32];     // 128B-strided per-CTA step flags

// ---------------- helpers ----------------
__device__ __forceinline__ uint32_t smem_u32(const void* p) {
    uint32_t a;
    asm("{ .reg .u64 t; cvta.to.shared.u64 t, %1; cvt.u32.u64 %0, t; }" : "=r"(a) : "l"(p));
    return a;
}
__device__ __forceinline__ void cp16(uint32_t dst, const void* src) {
    asm volatile("cp.async.cg.shared.global [%0], [%1], 16;"
                 :: "r"(dst), "l"(__cvta_generic_to_global(src)) : "memory");
}
__device__ __forceinline__ uint32_t sw128(uint32_t off) { return off ^ ((off >> 3) & 0x70); }
__device__ __forceinline__ void ldmat4(uint32_t addr, uint32_t& r0, uint32_t& r1,
                                       uint32_t& r2, uint32_t& r3) {
    asm volatile("ldmatrix.sync.aligned.m8n8.x4.shared.b16 {%0,%1,%2,%3}, [%4];"
                 : "=r"(r0), "=r"(r1), "=r"(r2), "=r"(r3) : "r"(addr));
}
__device__ __forceinline__ void mma_f16(float& d0, float& d1, float& d2, float& d3,
                                        uint32_t a0, uint32_t a1, uint32_t a2, uint32_t a3,
                                        uint32_t b0, uint32_t b1) {
    asm volatile("mma.sync.aligned.m16n8k16.row.col.f32.f16.f16.f32 "
                 "{%0,%1,%2,%3},{%4,%5,%6,%7},{%8,%9},{%0,%1,%2,%3};"
                 : "+f"(d0), "+f"(d1), "+f"(d2), "+f"(d3)
                 : "r"(a0), "r"(a1), "r"(a2), "r"(a3), "r"(b0), "r"(b1));
}
__device__ __forceinline__ void split_h(float x, uint32_t& hi, uint32_t& lo) {
    __half h = __float2half(x);
    __half l = __float2half(x - __half2float(h));
    hi = (uint32_t)__half_as_ushort(h);
    lo = (uint32_t)__half_as_ushort(l);
}

struct Ptrs {
    const __half *ah, *al, *hhp, *hlp, *w1, *w2;
};
__device__ __forceinline__ void get_ptrs(int step, Ptrs& P) {
    int t = step >> 2, j = step & 3;
    P.ah  = (j == 0) ? g_xh + (size_t)t * BH : g_curh[j & 1];
    P.al  = (j == 0) ? g_xl + (size_t)t * BH : g_curl[j & 1];
    P.hhp = g_hh[j][t & 1];
    P.hlp = g_hl[j][t & 1];
    P.w1  = g_w[0][j];
    P.w2  = g_w[1][j];
}
__device__ __forceinline__ const __half* selA(const Ptrs& P, int p) {
    return (p == 0) ? P.ah : (p == 1) ? P.al : (p == 2) ? P.hhp : P.hlp;
}
__device__ __forceinline__ const __half* selB(const Ptrs& P, int p) {
    return (p < 2) ? P.w1 : P.w2;
}

// ---------------- init kernels ----------------
__global__ void zero_state_kernel() {
    int i = blockIdx.x * blockDim.x + threadIdx.x;
    if (i < GRID_CTAS * 32) g_flags[i] = 0u;
    int nc = LAYERS * BH;
    int nh = LAYERS * 2 * BH / 2;      // u32 words in g_hh (and g_hl)
    if (i < nc) ((float*)g_c)[i] = 0.0f;
    if (i < nh) { ((uint32_t*)g_hh)[i] = 0u; ((uint32_t*)g_hl)[i] = 0u; }
}

__global__ void bias_perm_kernel(const float* __restrict__ bias) {
    int i = blockIdx.x * blockDim.x + threadIdx.x;
    if (i >= LAYERS * ZCOLS) return;
    int l = i >> 12, n = i & 4095;
    g_biasp[l][4 * (n & 1023) + (n >> 10)] = bias[i];
}

// transpose [1024,4096] -> fp16 [4096(gate-permuted)][1024]
__global__ void wconv_kernel(const float* __restrict__ kern, const float* __restrict__ rec) {
    __shared__ float t[32][33];
    int mat = blockIdx.z >> 2;
    int l   = blockIdx.z & 3;
    const float* src = (mat ? rec : kern) + (size_t)l * HID * ZCOLS;
    int n0 = blockIdx.x * 32, k0 = blockIdx.y * 32;
    int tx = threadIdx.x, ty = threadIdx.y;
    #pragma unroll
    for (int i = 0; i < 4; i++)
        t[ty + i * 8][tx] = src[(size_t)(k0 + ty + i * 8) * ZCOLS + n0 + tx];
    __syncthreads();
    __half* o = g_w[mat][l];
    #pragma unroll
    for (int i = 0; i < 4; i++) {
        int n  = n0 + ty + i * 8;
        int np = 4 * (n & 1023) + (n >> 10);
        o[(size_t)np * HID + k0 + tx] = __float2half(t[tx][ty + i * 8]);
    }
}

__global__ void xsplit_kernel(const float* __restrict__ x) {
    int i = blockIdx.x * blockDim.x + threadIdx.x;
    if (i >= T_STEPS * BH) return;
    float v = x[i];
    __half h = __float2half(v);
    g_xh[i] = h;
    g_xl[i] = __float2half(v - __half2float(h));
}

// ---------------- persistent fused LSTM ----------------
__global__ __launch_bounds__(256, 1) void lstm_persistent_kernel(float* __restrict__ out)
{
    extern __shared__ char smem[];
    const uint32_t sb = smem_u32(smem);
    const int tid  = threadIdx.x;
    const int lane = tid & 31;
    const int wid  = tid >> 5;
    const int wm = wid >> 2;
    const int wn = wid & 3;
    const int blockN   = blockIdx.x * 128;
    const int blockRow = blockIdx.y * 64;
    const int ctaid    = blockIdx.y * 32 + blockIdx.x;

    // cp.async load maps
    const int ld_row = tid >> 3;           // 0..31
    const int ld_c16 = tid & 7;            // 0..7
    uint32_t aDst[2], bDst[4];
    #pragma unroll
    for (int r = 0; r < 2; r++)
        aDst[r] = sw128((uint32_t)((ld_row + r * 32) * 128 + ld_c16 * 16));
    #pragma unroll
    for (int r = 0; r < 4; r++)
        bDst[r] = A_BYTES + sw128((uint32_t)((ld_row + r * 32) * 128 + ld_c16 * 16));

    // ldmatrix base offsets (XOR (ks&3)*32; panel offset added at use)
    uint32_t aBase[2], bBase[2];
    {
        int mA = wm * 32 + (lane & 7) + ((lane >> 3) & 1) * 8;
        int kA = (lane >> 4) * 16;
        int nB = wn * 32 + (lane & 7) + ((lane >> 4) & 1) * 8;
        int kB = ((lane >> 3) & 1) * 16;
        #pragma unroll
        for (int mi = 0; mi < 2; mi++) {
            int row = mA + mi * 16;
            aBase[mi] = (uint32_t)(row * 128) + ((uint32_t)kA ^ ((uint32_t)(row & 7) * 16));
        }
        #pragma unroll
        for (int nh2 = 0; nh2 < 2; nh2++) {
            int row = nB + nh2 * 16;
            bBase[nh2] = A_BYTES + (uint32_t)(row * 128) + ((uint32_t)kB ^ ((uint32_t)(row & 7) * 16));
        }
    }

    auto loadA = [&](const Ptrs& P, int jc, int s) {
        int p = jc >> 3, k0 = (jc & 7) * KC;
        const __half* As = selA(P, p);
        uint32_t base = sb + (uint32_t)s * STAGE_BYTES;
        #pragma unroll
        for (int pi = 0; pi < 2; pi++)
            #pragma unroll
            for (int r = 0; r < 2; r++)
                cp16(base + pi * A_PANEL + aDst[r],
                     As + (size_t)(blockRow + ld_row + r * 32) * HID + k0 + pi * 64 + ld_c16 * 8);
    };
    auto loadB = [&](const Ptrs& P, int jc, int s) {
        int p = jc >> 3, k0 = (jc & 7) * KC;
        const __half* Bs = selB(P, p);
        uint32_t base = sb + (uint32_t)s * STAGE_BYTES;
        #pragma unroll
        for (int pi = 0; pi < 2; pi++)
            #pragma unroll
            for (int r = 0; r < 4; r++)
                cp16(base + pi * B_PANEL + bDst[r],
                     Bs + (size_t)(blockN + ld_row + r * 32) * HID + k0 + pi * 64 + ld_c16 * 8);
    };

    auto ldsm_ks = [&](uint32_t base, int ks, uint32_t a[2][4], uint32_t bt[2][4]) {
        uint32_t xk  = (uint32_t)((ks & 3) * 32);
        uint32_t pkA = (uint32_t)((ks >> 2) * A_PANEL);
        uint32_t pkB = (uint32_t)((ks >> 2) * B_PANEL);
        #pragma unroll
        for (int mi = 0; mi < 2; mi++)
            ldmat4(base + pkA + (aBase[mi] ^ xk), a[mi][0], a[mi][1], a[mi][2], a[mi][3]);
        #pragma unroll
        for (int nh2 = 0; nh2 < 2; nh2++)
            ldmat4(base + pkB + (bBase[nh2] ^ xk), bt[nh2][0], bt[nh2][1], bt[nh2][2], bt[nh2][3]);
    };

    // prologue: prefetch chunks 0,1
    Ptrs P;
    get_ptrs(0, P);
    loadB(P, 0, 0); asm volatile("cp.async.commit_group;" ::: "memory");
    loadB(P, 1, 1); asm volatile("cp.async.commit_group;" ::: "memory");
    loadA(P, 0, 0); asm volatile("cp.async.commit_group;" ::: "memory");
    loadA(P, 1, 1); asm volatile("cp.async.commit_group;" ::: "memory");

    #pragma unroll 1
    for (int step = 0; step < NSTEPS; step++) {
        const int t = step >> 2;
        const int j = step & 3;
        get_ptrs(step, P);

        float d[2][4][4];
        #pragma unroll
        for (int mi = 0; mi < 2; mi++)
            #pragma unroll
            for (int ni = 0; ni < 4; ni++)
                #pragma unroll
                for (int r = 0; r < 4; r++) d[mi][ni][r] = 0.0f;

        int s_cmp = 0, s_load = 2;
        #pragma unroll 1
        for (int i = 0; i < NCHUNK; i++) {
            asm volatile("cp.async.wait_group 1;" ::: "memory");
            __syncthreads();
            if (i + 2 < NCHUNK) { loadA(P, i + 2, s_load); loadB(P, i + 2, s_load); }
            asm volatile("cp.async.commit_group;" ::: "memory");

            uint32_t base = sb + (uint32_t)s_cmp * STAGE_BYTES;
            uint32_t a[2][2][4], bt[2][2][4];
            ldsm_ks(base, 0, a[0], bt[0]);
            #pragma unroll
            for (int ks = 0; ks < 8; ks++) {
                int cur = ks & 1;
                if (ks < 7) ldsm_ks(base, ks + 1, a[cur ^ 1], bt[cur ^ 1]);
                #pragma unroll
                for (int mi = 0; mi < 2; mi++)
                    #pragma unroll
                    for (int ni = 0; ni < 4; ni++)
                        mma_f16(d[mi][ni][0], d[mi][ni][1], d[mi][ni][2], d[mi][ni][3],
                                a[cur][mi][0], a[cur][mi][1], a[cur][mi][2], a[cur][mi][3],
                                bt[cur][ni >> 1][(ni & 1) * 2], bt[cur][ni >> 1][(ni & 1) * 2 + 1]);
            }
            if (++s_cmp == 3) s_cmp = 0;
            if (++s_load == 3) s_load = 0;
        }

        asm volatile("cp.async.wait_group 0;" ::: "memory");
        __syncthreads();

        // stage accumulators: per-warp [32 rows][33 floats]
        float* st = (float*)(smem + (size_t)wid * 32 * 33 * 4);
        #pragma unroll
        for (int mi = 0; mi < 2; mi++) {
            int r0 = mi * 16 + (lane >> 2);
            #pragma unroll
            for (int ni = 0; ni < 4; ni++) {
                int c0 = ni * 8 + 2 * (lane & 3);
                st[r0 * 33 + c0]           = d[mi][ni][0];
                st[r0 * 33 + c0 + 1]       = d[mi][ni][1];
                st[(r0 + 8) * 33 + c0]     = d[mi][ni][2];
                st[(r0 + 8) * 33 + c0 + 1] = d[mi][ni][3];
            }
        }
        __syncwarp();

        // gate math
        {
            const float* zrow = st + lane * 33;
            const int m  = blockRow + wm * 32 + lane;
            const int ug = (blockN >> 2) + wn * 8;
            const float4* bq = (const float4*)(&g_biasp[j][blockN + wn * 32]);
            float* cp = &g_c[j][(size_t)m * HID + ug];
            float4 co0 = *(const float4*)(cp);
            float4 co1 = *(const float4*)(cp + 4);
            float cold[8] = {co0.x, co0.y, co0.z, co0.w, co1.x, co1.y, co1.z, co1.w};
            float cn[8], hn[8];
            #pragma unroll
            for (int k = 0; k < 8; k++) {
                float4 bb = bq[k];
                float zi = zrow[4 * k]     + bb.x;
                float zf = zrow[4 * k + 1] + bb.y;
                float zg = zrow[4 * k + 2] + bb.z;
                float zo = zrow[4 * k + 3] + bb.w;
                float ig = 1.0f / (1.0f + __expf(-zi));
                float fg = 1.0f / (1.0f + __expf(-zf));
                float gg = tanhf(zg);
                float og = 1.0f / (1.0f + __expf(-zo));
                float c_ = fg * cold[k] + ig * gg;
                cn[k] = c_;
                hn[k] = og * tanhf(c_);
            }
            *(float4*)(cp)     = make_float4(cn[0], cn[1], cn[2], cn[3]);
            *(float4*)(cp + 4) = make_float4(cn[4], cn[5], cn[6], cn[7]);

            uint32_t chi[8], clo[8], hhi[8], hlo[8];
            #pragma unroll
            for (int k = 0; k < 8; k++) {
                split_h(cn[k], chi[k], clo[k]);
                split_h(hn[k], hhi[k], hlo[k]);
            }
            size_t so = (size_t)m * HID + ug;
            __half* curh_o = g_curh[(j + 1) & 1];
            __half* curl_o = g_curl[(j + 1) & 1];
            __half* hh_o   = g_hh[j][(t + 1) & 1];
            __half* hl_o   = g_hl[j][(t + 1) & 1];
            uint4 v;
            v = make_uint4(chi[0] | (chi[1] << 16), chi[2] | (chi[3] << 16),
                           chi[4] | (chi[5] << 16), chi[6] | (chi[7] << 16));
            *(uint4*)(curh_o + so) = v;
            v = make_uint4(clo[0] | (clo[1] << 16), clo[2] | (clo[3] << 16),
                           clo[4] | (clo[5] << 16), clo[6] | (clo[7] << 16));
            *(uint4*)(curl_o + so) = v;
            v = make_uint4(hhi[0] | (hhi[1] << 16), hhi[2] | (hhi[3] << 16),
                           hhi[4] | (hhi[5] << 16), hhi[6] | (hhi[7] << 16));
            *(uint4*)(hh_o + so) = v;
            v = make_uint4(hlo[0] | (hlo[1] << 16), hlo[2] | (hlo[3] << 16),
                           hlo[4] | (hlo[5] << 16), hlo[6] | (hlo[7] << 16));
            *(uint4*)(hl_o + so) = v;

            if (step == NSTEPS - 1) {
                *(float4*)(out + so)     = make_float4(cn[0], cn[1], cn[2], cn[3]);
                *(float4*)(out + so + 4) = make_float4(cn[4], cn[5], cn[6], cn[7]);
            }
        }

        // -------- distributed-flag barrier + cross-step prefetch --------
        if (step < NSTEPS - 1) {
            __syncthreads();   // all epilogue stores issued before signaling
            // signal own arrival (release publishes this CTA's state stores)
            if (tid == 0)
                asm volatile("st.release.gpu.global.u32 [%0], %1;"
                             :: "l"(&g_flags[ctaid * 32]), "r"((unsigned)(step + 1)) : "memory");
            Ptrs Pn;
            get_ptrs(step + 1, Pn);
            // weights are state-independent: prefetch while other CTAs arrive
            loadB(Pn, 0, 0); asm volatile("cp.async.commit_group;" ::: "memory");
            loadB(Pn, 1, 1); asm volatile("cp.async.commit_group;" ::: "memory");
            // parallel poll: thread i waits for CTA i's flag
            if (tid < GRID_CTAS) {
                unsigned v;
                do {
                    asm volatile("ld.acquire.gpu.global.u32 %0, [%1];"
                                 : "=r"(v) : "l"(&g_flags[tid * 32]));
                } while (v < (unsigned)(step + 1));
            }
            __syncthreads();
            // activations depend on the step we just synced on
            loadA(Pn, 0, 0); asm volatile("cp.async.commit_group;" ::: "memory");
            loadA(Pn, 1, 1); asm volatile("cp.async.commit_group;" ::: "memory");
        }
    }
}

// ---------------- host launcher ----------------
extern "C" void kernel_launch(void* const* d_in, const int* in_sizes, int n_in,
                              void* d_out, int out_size)
{
    const float* inputs = (const float*)d_in[0];
    const float* kernel = (const float*)d_in[1];
    const float* rec    = (const float*)d_in[2];
    const float* bias   = (const float*)d_in[3];
    float* out = (float*)d_out;

    cudaFuncSetAttribute(lstm_persistent_kernel,
                         cudaFuncAttributeMaxDynamicSharedMemorySize, SMEM_BYTES);

    {
        int n = LAYERS * BH;
        zero_state_kernel<<<(n + 255) / 256, 256>>>();
        bias_perm_kernel<<<(LAYERS * ZCOLS + 255) / 256, 256>>>(bias);
        wconv_kernel<<<dim3(ZCOLS / 32, HID / 32, 2 * LAYERS), dim3(32, 8)>>>(kernel, rec);
        xsplit_kernel<<<(T_STEPS * BH + 255) / 256, 256>>>(inputs);
    }

    dim3 grid(32, 4);   // 128 CTAs, all resident — required by the barrier
    lstm_persistent_kernel<<<grid, 256, SMEM_BYTES>>>(out);
}